// round 1
// baseline (speedup 1.0000x reference)
#include <cuda_runtime.h>

// ---------------- model constants ----------------
#define U_DIM 768
#define T_DIM 1024
#define B_DIM 2
#define BT    2048          // B*T
#define E_DIM 8
#define L_DIM 16
#define V_DIM 32000
#define EPS_F 1e-6f

// ---------------- GEMM tiling ----------------
#define BM 64
#define BN 64
#define BK 16
#define TM 8
#define TN 4
#define GEMM_THREADS 128    // (BM/TM)*(BN/TN) = 8*16

// ---------------- scratch (static device memory; no runtime alloc) ----------------
__device__ float g_h0 [BT * U_DIM];
__device__ float g_h  [BT * U_DIM];
__device__ float g_inp[BT * U_DIM];
__device__ float g_n  [BT * U_DIM];
__device__ float g_q  [BT * U_DIM];
__device__ float g_k  [BT * U_DIM];
__device__ float g_v  [BT * U_DIM];
__device__ float g_tmp[BT * U_DIM];
__device__ float g_kv [B_DIM * U_DIM * U_DIM];
__device__ float g_ksum[B_DIM * U_DIM];
__device__ float g_den[BT];
__device__ float g_gate[BT * E_DIM];

// ---------------- helpers ----------------
__device__ __forceinline__ float warpSum(float v) {
    #pragma unroll
    for (int o = 16; o > 0; o >>= 1) v += __shfl_xor_sync(0xffffffffu, v, o);
    return v;
}

// ---------------- generic GEMM with fused epilogues ----------------
// EPI 0: C = acc*scale + bias[n]
// EPI 1: C = phi(acc + bias) = (t>0 ? t+1 : exp(t))          (elu+1)
// EPI 2: C = sigmoid(acc + bias)
// EPI 3: C = sigmoid(acc + bias) + aux1[idx] + aux2[idx]
// EPI 4: C = acc / aux1[row] + aux2[idx]                      (attention num/den + residual)
template<int EPI>
__global__ __launch_bounds__(GEMM_THREADS)
void gemm_kernel(const float* __restrict__ A, const float* __restrict__ B, float* C,
                 int M, int N, int K, int transA,
                 long aStrideZ, long bStrideZ, long cStrideZ,
                 const float* __restrict__ bias, long biasStrideZ,
                 const float* aux1, long aux1StrideZ,
                 const float* aux2, long aux2StrideZ,
                 float scale)
{
    int z = blockIdx.z;
    A += z * aStrideZ;
    B += z * bStrideZ;
    C += z * cStrideZ;
    if (bias) bias += z * biasStrideZ;
    if (aux1) aux1 += z * aux1StrideZ;
    if (aux2) aux2 += z * aux2StrideZ;

    __shared__ float As[BK][BM + 4];
    __shared__ float Bs[BK][BN + 4];

    const int tid = threadIdx.x;
    const int tm  = tid >> 4;     // 0..7
    const int tn  = tid & 15;     // 0..15
    const int row0 = blockIdx.y * BM;
    const int col0 = blockIdx.x * BN;

    float acc[TM][TN];
    #pragma unroll
    for (int i = 0; i < TM; i++)
        #pragma unroll
        for (int j = 0; j < TN; j++) acc[i][j] = 0.f;

    for (int k0 = 0; k0 < K; k0 += BK) {
        if (!transA) {
            // A is [M,K] row-major (lda = K)
            #pragma unroll
            for (int t = 0; t < 2; t++) {
                int idx = tid + t * GEMM_THREADS;  // 0..255
                int r   = idx >> 2;                // 0..63
                int c4  = idx & 3;                 // 0..3
                float4 v4 = *(const float4*)(A + (long)(row0 + r) * K + k0 + c4 * 4);
                As[c4 * 4 + 0][r] = v4.x;
                As[c4 * 4 + 1][r] = v4.y;
                As[c4 * 4 + 2][r] = v4.z;
                As[c4 * 4 + 3][r] = v4.w;
            }
        } else {
            // A is [K,M] row-major (lda = M)
            #pragma unroll
            for (int t = 0; t < 2; t++) {
                int idx = tid + t * GEMM_THREADS;
                int kk  = idx >> 4;                // 0..15
                int m4  = idx & 15;                // 0..15
                float4 v4 = *(const float4*)(A + (long)(k0 + kk) * M + row0 + m4 * 4);
                *(float4*)&As[kk][m4 * 4] = v4;
            }
        }
        // B is [K,N] row-major
        #pragma unroll
        for (int t = 0; t < 2; t++) {
            int idx = tid + t * GEMM_THREADS;
            int kk  = idx >> 4;
            int n4  = idx & 15;
            float4 v4 = *(const float4*)(B + (long)(k0 + kk) * N + col0 + n4 * 4);
            *(float4*)&Bs[kk][n4 * 4] = v4;
        }
        __syncthreads();

        #pragma unroll
        for (int kk = 0; kk < BK; kk++) {
            float ra[TM], rb[TN];
            #pragma unroll
            for (int i = 0; i < TM; i++) ra[i] = As[kk][tm * TM + i];
            #pragma unroll
            for (int j = 0; j < TN; j++) rb[j] = Bs[kk][tn * TN + j];
            #pragma unroll
            for (int i = 0; i < TM; i++)
                #pragma unroll
                for (int j = 0; j < TN; j++)
                    acc[i][j] = fmaf(ra[i], rb[j], acc[i][j]);
        }
        __syncthreads();
    }

    // epilogue
    #pragma unroll
    for (int i = 0; i < TM; i++) {
        int r = row0 + tm * TM + i;
        #pragma unroll
        for (int j = 0; j < TN; j++) {
            int c = col0 + tn * TN + j;
            long idx = (long)r * N + c;
            float a = acc[i][j];
            float b = bias ? bias[c] : 0.f;
            float o;
            if (EPI == 0) {
                o = a * scale + b;
            } else if (EPI == 1) {
                float t = a + b;
                o = (t > 0.f) ? (t + 1.f) : __expf(t);
            } else if (EPI == 2) {
                float t = a + b;
                o = 1.f / (1.f + __expf(-t));
            } else if (EPI == 3) {
                float t = a + b;
                o = 1.f / (1.f + __expf(-t)) + aux1[idx] + aux2[idx];
            } else { // EPI == 4
                o = a / aux1[r] + aux2[idx];
            }
            C[idx] = o;
        }
    }
}

// ---------------- MoE GEMM: h[t,:] = sum_e gate[t,e] * (n @ eW_e + eb_e) ----------------
__global__ __launch_bounds__(GEMM_THREADS)
void moe_kernel(const float* __restrict__ A,      // n [BT,U]
                const float* __restrict__ Bex,    // eW_l [E,U,U]
                const float* __restrict__ ebias,  // eb_l [E,U]
                const float* __restrict__ gate,   // [BT,E]
                float* C,                         // h   [BT,U]
                int M, int N, int K)
{
    __shared__ float As[BK][BM + 4];
    __shared__ float Bs[BK][BN + 4];

    const int tid = threadIdx.x;
    const int tm  = tid >> 4;
    const int tn  = tid & 15;
    const int row0 = blockIdx.y * BM;
    const int col0 = blockIdx.x * BN;

    float total[TM][TN];
    #pragma unroll
    for (int i = 0; i < TM; i++)
        #pragma unroll
        for (int j = 0; j < TN; j++) total[i][j] = 0.f;

    for (int e = 0; e < E_DIM; e++) {
        const float* B = Bex + (long)e * K * N;
        float acc[TM][TN];
        #pragma unroll
        for (int i = 0; i < TM; i++)
            #pragma unroll
            for (int j = 0; j < TN; j++) acc[i][j] = 0.f;

        for (int k0 = 0; k0 < K; k0 += BK) {
            #pragma unroll
            for (int t = 0; t < 2; t++) {
                int idx = tid + t * GEMM_THREADS;
                int r   = idx >> 2;
                int c4  = idx & 3;
                float4 v4 = *(const float4*)(A + (long)(row0 + r) * K + k0 + c4 * 4);
                As[c4 * 4 + 0][r] = v4.x;
                As[c4 * 4 + 1][r] = v4.y;
                As[c4 * 4 + 2][r] = v4.z;
                As[c4 * 4 + 3][r] = v4.w;
            }
            #pragma unroll
            for (int t = 0; t < 2; t++) {
                int idx = tid + t * GEMM_THREADS;
                int kk  = idx >> 4;
                int n4  = idx & 15;
                float4 v4 = *(const float4*)(B + (long)(k0 + kk) * N + col0 + n4 * 4);
                *(float4*)&Bs[kk][n4 * 4] = v4;
            }
            __syncthreads();
            #pragma unroll
            for (int kk = 0; kk < BK; kk++) {
                float ra[TM], rb[TN];
                #pragma unroll
                for (int i = 0; i < TM; i++) ra[i] = As[kk][tm * TM + i];
                #pragma unroll
                for (int j = 0; j < TN; j++) rb[j] = Bs[kk][tn * TN + j];
                #pragma unroll
                for (int i = 0; i < TM; i++)
                    #pragma unroll
                    for (int j = 0; j < TN; j++)
                        acc[i][j] = fmaf(ra[i], rb[j], acc[i][j]);
            }
            __syncthreads();
        }

        #pragma unroll
        for (int i = 0; i < TM; i++) {
            float g = gate[(long)(row0 + tm * TM + i) * E_DIM + e];
            #pragma unroll
            for (int j = 0; j < TN; j++) {
                float bj = ebias[(long)e * N + col0 + tn * TN + j];
                total[i][j] = fmaf(g, acc[i][j] + bj, total[i][j]);
            }
        }
    }

    #pragma unroll
    for (int i = 0; i < TM; i++) {
        int r = row0 + tm * TM + i;
        #pragma unroll
        for (int j = 0; j < TN; j++)
            C[(long)r * N + col0 + tn * TN + j] = total[i][j];
    }
}

// ---------------- small kernels ----------------
__global__ __launch_bounds__(192)
void gather_kernel(const int* __restrict__ x, const float* __restrict__ emb, float* xe)
{
    int row = blockIdx.x;
    int tok = x[row];
    const float4* src = (const float4*)(emb + (long)tok * U_DIM);
    float4* dst = (float4*)(xe + (long)row * U_DIM);
    for (int i = threadIdx.x; i < U_DIM / 4; i += blockDim.x) dst[i] = src[i];
}

__global__ __launch_bounds__(256)
void rms_kernel(const float* __restrict__ h, float* out)
{
    long row = blockIdx.x;
    const float* hr = h + row * U_DIM;
    float s = 0.f;
    for (int u = threadIdx.x; u < U_DIM; u += 256) { float t = hr[u]; s = fmaf(t, t, s); }
    s = warpSum(s);
    __shared__ float red[8];
    __shared__ float rsh;
    int wid = threadIdx.x >> 5, lane = threadIdx.x & 31;
    if (lane == 0) red[wid] = s;
    __syncthreads();
    if (threadIdx.x == 0) {
        float tot = 0.f;
        #pragma unroll
        for (int i = 0; i < 8; i++) tot += red[i];
        rsh = rsqrtf(tot / (float)U_DIM + EPS_F);
    }
    __syncthreads();
    float r = rsh;
    for (int u = threadIdx.x; u < U_DIM; u += 256) out[row * U_DIM + u] = hr[u] * r;
}

__global__ __launch_bounds__(256)
void colsum_kernel(const float* __restrict__ kbuf, float* ks)
{
    int b = blockIdx.y;
    int u = blockIdx.x * 256 + threadIdx.x;
    const float* kb = kbuf + (long)b * T_DIM * U_DIM;
    float s = 0.f;
    for (int t = 0; t < T_DIM; t++) s += kb[(long)t * U_DIM + u];
    ks[b * U_DIM + u] = s;
}

__global__ __launch_bounds__(256)
void den_kernel(const float* __restrict__ q, const float* __restrict__ ks, float* den)
{
    int gwarp = (blockIdx.x * blockDim.x + threadIdx.x) >> 5;
    int lane  = threadIdx.x & 31;
    if (gwarp >= BT) return;
    int b = gwarp / T_DIM;
    const float* qr = q + (long)gwarp * U_DIM;
    const float* kb = ks + b * U_DIM;
    float s = 0.f;
    for (int u = lane; u < U_DIM; u += 32) s = fmaf(qr[u], kb[u], s);
    s = warpSum(s);
    if (lane == 0) den[gwarp] = s + EPS_F;
}

__global__ __launch_bounds__(256)
void gate_kernel(const float* __restrict__ n, const float* __restrict__ gWl,
                 const float* __restrict__ gbl, float* gate)
{
    int row = blockIdx.x;
    int wid = threadIdx.x >> 5, lane = threadIdx.x & 31;
    const float* nr = n + (long)row * U_DIM;
    float s = 0.f;
    for (int u = lane; u < U_DIM; u += 32) s = fmaf(nr[u], gWl[u * E_DIM + wid], s);
    s = warpSum(s);
    __shared__ float sl[E_DIM];
    if (lane == 0) sl[wid] = s + gbl[wid];
    __syncthreads();
    if (threadIdx.x == 0) {
        float mx = sl[0];
        #pragma unroll
        for (int e = 1; e < E_DIM; e++) mx = fmaxf(mx, sl[e]);
        float ex[E_DIM], sum = 0.f;
        #pragma unroll
        for (int e = 0; e < E_DIM; e++) { ex[e] = __expf(sl[e] - mx); sum += ex[e]; }
        float inv = 1.f / sum;
        #pragma unroll
        for (int e = 0; e < E_DIM; e++) gate[(long)row * E_DIM + e] = ex[e] * inv;
    }
}

__global__ __launch_bounds__(256)
void add_kernel(const float* __restrict__ a, const float* __restrict__ b, float* c, int n)
{
    int i = blockIdx.x * blockDim.x + threadIdx.x;
    if (i < n) c[i] = a[i] + b[i];
}

// ---------------- host-side GEMM dispatch ----------------
typedef const float* cfp;
static void gemm(int epi, cfp A, cfp B, float* C, int M, int N, int K,
                 int transA, long az, long bz, long cz, int Z,
                 cfp bias, long biasz, cfp aux1, long a1z, cfp aux2, long a2z,
                 float scale)
{
    dim3 grid(N / BN, M / BM, Z);
    dim3 block(GEMM_THREADS);
    switch (epi) {
    case 0: gemm_kernel<0><<<grid, block>>>(A, B, C, M, N, K, transA, az, bz, cz, bias, biasz, aux1, a1z, aux2, a2z, scale); break;
    case 1: gemm_kernel<1><<<grid, block>>>(A, B, C, M, N, K, transA, az, bz, cz, bias, biasz, aux1, a1z, aux2, a2z, scale); break;
    case 2: gemm_kernel<2><<<grid, block>>>(A, B, C, M, N, K, transA, az, bz, cz, bias, biasz, aux1, a1z, aux2, a2z, scale); break;
    case 3: gemm_kernel<3><<<grid, block>>>(A, B, C, M, N, K, transA, az, bz, cz, bias, biasz, aux1, a1z, aux2, a2z, scale); break;
    case 4: gemm_kernel<4><<<grid, block>>>(A, B, C, M, N, K, transA, az, bz, cz, bias, biasz, aux1, a1z, aux2, a2z, scale); break;
    }
}

// ---------------- entry point ----------------
extern "C" void kernel_launch(void* const* d_in, const int* in_sizes, int n_in,
                              void* d_out, int out_size)
{
    const int*   x    = (const int*)  d_in[0];
    const float* emb  = (const float*)d_in[1];
    const float* W_in = (const float*)d_in[2];
    const float* Wq   = (const float*)d_in[3];
    const float* bq   = (const float*)d_in[4];
    const float* Wk   = (const float*)d_in[5];
    const float* bk   = (const float*)d_in[6];
    const float* Wv   = (const float*)d_in[7];
    const float* bv   = (const float*)d_in[8];
    const float* gW   = (const float*)d_in[9];
    const float* gb   = (const float*)d_in[10];
    const float* eW   = (const float*)d_in[11];
    const float* eb   = (const float*)d_in[12];
    const float* fW1  = (const float*)d_in[13];
    const float* fb1  = (const float*)d_in[14];
    const float* fW2  = (const float*)d_in[15];
    const float* fb2  = (const float*)d_in[16];
    const float* Wlog = (const float*)d_in[17];
    float* out = (float*)d_out;

    float *h0, *h, *inp, *n, *q, *k, *v, *tmp, *kv, *ksum, *den, *gate;
    cudaGetSymbolAddress((void**)&h0,   g_h0);
    cudaGetSymbolAddress((void**)&h,    g_h);
    cudaGetSymbolAddress((void**)&inp,  g_inp);
    cudaGetSymbolAddress((void**)&n,    g_n);
    cudaGetSymbolAddress((void**)&q,    g_q);
    cudaGetSymbolAddress((void**)&k,    g_k);
    cudaGetSymbolAddress((void**)&v,    g_v);
    cudaGetSymbolAddress((void**)&tmp,  g_tmp);
    cudaGetSymbolAddress((void**)&kv,   g_kv);
    cudaGetSymbolAddress((void**)&ksum, g_ksum);
    cudaGetSymbolAddress((void**)&den,  g_den);
    cudaGetSymbolAddress((void**)&gate, g_gate);

    const long TU = (long)T_DIM * U_DIM;
    const long UU = (long)U_DIM * U_DIM;
    const size_t HB = sizeof(float) * (size_t)BT * U_DIM;

    // h0 = emb[x] @ W_in ; h = h0
    gather_kernel<<<BT, 192>>>(x, emb, tmp);
    gemm(0, tmp, W_in, h0, BT, U_DIM, U_DIM, 0, 0, 0, 0, 1,
         nullptr, 0, nullptr, 0, nullptr, 0, 1.f);
    cudaMemcpyAsync(h, h0, HB, cudaMemcpyDeviceToDevice, 0);

    for (int l = 0; l < L_DIM; l++) {
        cfp Wq_l = Wq + (long)l * UU,  bq_l = bq + l * U_DIM;
        cfp Wk_l = Wk + (long)l * UU,  bk_l = bk + l * U_DIM;
        cfp Wv_l = Wv + (long)l * UU,  bv_l = bv + l * U_DIM;
        cfp gW_l = gW + (long)l * U_DIM * E_DIM, gb_l = gb + l * E_DIM;
        cfp eW_l = eW + (long)l * E_DIM * UU,    eb_l = eb + (long)l * E_DIM * U_DIM;
        cfp fW1_l = fW1 + (long)l * UU, fb1_l = fb1 + l * U_DIM;
        cfp fW2_l = fW2 + (long)l * UU, fb2_l = fb2 + l * U_DIM;

        cudaMemcpyAsync(inp, h, HB, cudaMemcpyDeviceToDevice, 0);

        // --- linear attention + residual ---
        rms_kernel<<<BT, 256>>>(h, n);
        gemm(1, n, Wq_l, q, BT, U_DIM, U_DIM, 0, 0, 0, 0, 1, bq_l, 0, nullptr, 0, nullptr, 0, 1.f);
        gemm(1, n, Wk_l, k, BT, U_DIM, U_DIM, 0, 0, 0, 0, 1, bk_l, 0, nullptr, 0, nullptr, 0, 1.f);
        gemm(0, n, Wv_l, v, BT, U_DIM, U_DIM, 0, 0, 0, 0, 1, bv_l, 0, nullptr, 0, nullptr, 0, 1.f);
        // kv[b] = k_b^T @ v_b   (M=U, N=U, K=T, batched over z)
        gemm(0, k, v, kv, U_DIM, U_DIM, T_DIM, 1, TU, TU, UU, B_DIM,
             nullptr, 0, nullptr, 0, nullptr, 0, 1.f);
        colsum_kernel<<<dim3(U_DIM / 256, B_DIM), 256>>>(k, ksum);
        den_kernel<<<BT / 8, 256>>>(q, ksum, den);
        // h = (q @ kv) / den + h   (batched over z)
        gemm(4, q, kv, h, T_DIM, U_DIM, U_DIM, 0, TU, UU, TU, B_DIM,
             nullptr, 0, den, T_DIM, h, TU, 1.f);

        // --- soft MoE (replaces h) ---
        rms_kernel<<<BT, 256>>>(h, n);
        gate_kernel<<<BT, 256>>>(n, gW_l, gb_l, gate);
        moe_kernel<<<dim3(U_DIM / BN, BT / BM), GEMM_THREADS>>>(n, eW_l, eb_l, gate, h,
                                                                BT, U_DIM, U_DIM);

        // --- sigmoid MLP + residual + outer residual ---
        rms_kernel<<<BT, 256>>>(h, n);
        gemm(2, n, fW1_l, tmp, BT, U_DIM, U_DIM, 0, 0, 0, 0, 1, fb1_l, 0, nullptr, 0, nullptr, 0, 1.f);
        // h = sigmoid(tmp @ fW2 + fb2) + h + inp
        gemm(3, tmp, fW2_l, h, BT, U_DIM, U_DIM, 0, 0, 0, 0, 1, fb2_l, 0, h, 0, inp, 0, 1.f);
    }

    // final: h = rms(h) + h0; h = rms(h); out = (h @ Wlog) / TEMP
    rms_kernel<<<BT, 256>>>(h, n);
    add_kernel<<<(BT * U_DIM) / 256, 256>>>(n, h0, h, BT * U_DIM);
    rms_kernel<<<BT, 256>>>(h, n);
    gemm(0, n, Wlog, out, BT, V_DIM, U_DIM, 0, 0, 0, 0, 1,
         nullptr, 0, nullptr, 0, nullptr, 0, 2.0f);
}